// round 17
// baseline (speedup 1.0000x reference)
#include <cuda_runtime.h>
#include <cstdint>
#include <cstddef>

#define N_PTS     200000
#define F_DIM     64
#define K_CL      256
#define MAX_ITERS 10
#define NSEG      256                              /* sort segments */
#define CHUNKB    ((N_PTS + NSEG - 1) / NSEG)      /* 782 */
#define NTILE     (N_PTS / 64)                     /* 3125 tiles of 64 points */
#define FLT_BIG   3.402823466e38f

/* smem layout */
#define C_GRP_STRIDE 514                           /* 8 cpairs*64 u64 + 2 pad */
#define C_TOTAL      (16 * C_GRP_STRIDE)           /* 8224 u64 = 64.3 KB      */
#define X_STRIDE_F   65                            /* odd => conflict-free    */

typedef unsigned long long u64;

// ---------------- device scratch (static: no runtime allocation) ----------------
__device__ __align__(16) float g_centers[K_CL * F_DIM];
__device__ float g_xsq[N_PTS];
__device__ int   g_order[N_PTS];                 // points sorted stably by label
__device__ int   g_bhist[NSEG][K_CL];
__device__ int   g_bbase[NSEG][K_CL];
__device__ int   g_counts[K_CL];
__device__ int   g_cbase[K_CL];

// ---------------- f32x2 helpers: per-lane IEEE fp32 rn (== scalar fmaf per lane) --
__device__ __forceinline__ u64 splat2(float v) {
    u64 r; asm("mov.b64 %0, {%1,%1};" : "=l"(r) : "f"(v)); return r;
}
__device__ __forceinline__ void unpack2(u64 v, float& lo, float& hi) {
    asm("mov.b64 {%0,%1}, %2;" : "=f"(lo), "=f"(hi) : "l"(v));
}
__device__ __forceinline__ u64 fma2(u64 a, u64 b, u64 c) {
    u64 d; asm("fma.rn.f32x2 %0, %1, %2, %3;" : "=l"(d) : "l"(a), "l"(b), "l"(c)); return d;
}

// ---------------- row reduce of sum(v*v): Neoverse V2 LV shape (VERIFIED R14) -----
// VF=4, IC=4, FUSED fmla, ((a0+a1)+a2)+a3 per lane, faddp (s0+s1)+(s2+s3).
// DO NOT CHANGE — bit-exact vs reference.
__device__ __forceinline__ float rowsq_ref(const float* __restrict__ r) {
    float A0[4] = {0.f, 0.f, 0.f, 0.f};
    float A1[4] = {0.f, 0.f, 0.f, 0.f};
    float A2[4] = {0.f, 0.f, 0.f, 0.f};
    float A3[4] = {0.f, 0.f, 0.f, 0.f};
#pragma unroll
    for (int i = 0; i < F_DIM / 16; i++) {
#pragma unroll
        for (int l = 0; l < 4; l++) {
            float v0 = r[16 * i + 0  + l];
            float v1 = r[16 * i + 4  + l];
            float v2 = r[16 * i + 8  + l];
            float v3 = r[16 * i + 12 + l];
            A0[l] = __fmaf_rn(v0, v0, A0[l]);
            A1[l] = __fmaf_rn(v1, v1, A1[l]);
            A2[l] = __fmaf_rn(v2, v2, A2[l]);
            A3[l] = __fmaf_rn(v3, v3, A3[l]);
        }
    }
    float s[4];
#pragma unroll
    for (int l = 0; l < 4; l++)
        s[l] = __fadd_rn(__fadd_rn(__fadd_rn(A0[l], A1[l]), A2[l]), A3[l]);
    return __fadd_rn(__fadd_rn(s[0], s[1]), __fadd_rn(s[2], s[3]));
}

// ---------------- init: copy centers; xsq[n] computed ONCE (matches reference) ----
__global__ void k_init(const float* __restrict__ x, const float* __restrict__ c0) {
    int i = blockIdx.x * blockDim.x + threadIdx.x;
    if (i < K_CL * F_DIM) g_centers[i] = c0[i];
    if (i < N_PTS) g_xsq[i] = rowsq_ref(x + (size_t)i * F_DIM);
}

// ---------------- assignment (csq fused into prologue) ----------------------------
// Block tile: 64 points x 256 centers. 512 threads = 16 warps.
// Warp w = center group g (16 centers); lane q owns points q and q+32.
// Thread = 2 points x 8 center-pairs: 32 u64 accumulators acc[pt][j2],
// lanes = (center 16g+2j2, 16g+2j2+1).
// Centers pre-packed pairwise in smem (warp-uniform LDS.128 broadcast);
// x read as scalar LDS.32 at odd stride 65 (conflict-free), splat in regs.
// Per (point,center): UNCHANGED serial fused fma2 chain over f=0..63 ascending.
__global__ void __launch_bounds__(512, 1) k_assign(
        const float* __restrict__ x, float* __restrict__ labels) {
    extern __shared__ unsigned char dynsmem[];
    u64*   csp = (u64*)dynsmem;                      // [16 grp][514] packed pairs
    float* xsm = (float*)(csp + C_TOTAL);            // [64 pts][65]
    float* scq = xsm + 64 * X_STRIDE_F;              // [256]
    float* sbv = scq + K_CL;                         // [64 pts][17]
    int*   sbi = (int*)(sbv + 64 * 17);              // [64 pts][17]

    const int tid = threadIdx.x;
    const int g   = tid >> 5;                        // center group = warp id
    const int q   = tid & 31;                        // point lane

    // prologue: pairwise-packed centers + fused csq (identical rowsq_ref)
    for (int i = tid; i < K_CL * F_DIM; i += 512) {
        int c = i >> 6, f = i & 63;
        ((float*)csp)[(((c >> 4) * C_GRP_STRIDE + ((c & 15) >> 1) * 64 + f) << 1)
                      + (c & 1)] = g_centers[i];
    }
    for (int k = tid; k < K_CL; k += 512)
        scq[k] = rowsq_ref(g_centers + k * F_DIM);
    __syncthreads();

    const u64*   cbase = csp + g * C_GRP_STRIDE;
    const float* xr0   = xsm + q * X_STRIDE_F;
    const float* xr1   = xsm + (q + 32) * X_STRIDE_F;

    for (int T = blockIdx.x; T < NTILE; T += gridDim.x) {
        const int n0 = T * 64;
        // ---- stage x tile (64 rows x 64 f), row stride 65 floats ----
        {
            int p = tid >> 3, cs = tid & 7;          // 8 threads per row
            const float4* rr = (const float4*)(x + (size_t)(n0 + p) * F_DIM) + cs * 2;
            float4 v0 = rr[0], v1 = rr[1];
            float* dst = xsm + p * X_STRIDE_F + cs * 8;
            dst[0] = v0.x; dst[1] = v0.y; dst[2] = v0.z; dst[3] = v0.w;
            dst[4] = v1.x; dst[5] = v1.y; dst[6] = v1.z; dst[7] = v1.w;
        }
        float xsqA = g_xsq[n0 + q];
        float xsqB = g_xsq[n0 + q + 32];
        __syncthreads();

        // ---- mainloop: 32 chains, serial f-ascending fused fma2 ----
        u64 accA[8], accB[8];
#pragma unroll
        for (int j = 0; j < 8; j++) { accA[j] = 0ull; accB[j] = 0ull; }

#pragma unroll 4
        for (int f2 = 0; f2 < F_DIM / 2; f2++) {
            u64 xa0 = splat2(xr0[2 * f2]);           // point q,   f = 2f2
            u64 xa1 = splat2(xr0[2 * f2 + 1]);       // point q,   f = 2f2+1
            u64 xb0 = splat2(xr1[2 * f2]);           // point q+32
            u64 xb1 = splat2(xr1[2 * f2 + 1]);
#pragma unroll
            for (int j2 = 0; j2 < 8; j2++) {
                ulonglong2 cj = *(const ulonglong2*)(cbase + j2 * 64 + 2 * f2);
                accA[j2] = fma2(xa0, cj.x, accA[j2]);   // f = 2f2
                accA[j2] = fma2(xa1, cj.y, accA[j2]);   // f = 2f2+1
                accB[j2] = fma2(xb0, cj.x, accB[j2]);
                accB[j2] = fma2(xb1, cj.y, accB[j2]);
            }
        }

        // ---- epilogue: exact (xsq - 2*dot) + csq, strict < ascending k ----
        {
            float bv = FLT_BIG; int bi = 0;
#pragma unroll
            for (int j2 = 0; j2 < 8; j2++) {
                float d0, d1; unpack2(accA[j2], d0, d1);
                int k0 = 16 * g + 2 * j2;
                float e0 = __fadd_rn(__fmaf_rn(d0, -2.0f, xsqA), scq[k0]);
                float e1 = __fadd_rn(__fmaf_rn(d1, -2.0f, xsqA), scq[k0 + 1]);
                if (e0 < bv) { bv = e0; bi = k0; }
                if (e1 < bv) { bv = e1; bi = k0 + 1; }
            }
            sbv[q * 17 + g] = bv; sbi[q * 17 + g] = bi;
        }
        {
            float bv = FLT_BIG; int bi = 0;
#pragma unroll
            for (int j2 = 0; j2 < 8; j2++) {
                float d0, d1; unpack2(accB[j2], d0, d1);
                int k0 = 16 * g + 2 * j2;
                float e0 = __fadd_rn(__fmaf_rn(d0, -2.0f, xsqB), scq[k0]);
                float e1 = __fadd_rn(__fmaf_rn(d1, -2.0f, xsqB), scq[k0 + 1]);
                if (e0 < bv) { bv = e0; bi = k0; }
                if (e1 < bv) { bv = e1; bi = k0 + 1; }
            }
            sbv[(q + 32) * 17 + g] = bv; sbi[(q + 32) * 17 + g] = bi;
        }
        __syncthreads();

        // ---- final per-point argmin over groups (ascending => first-min) ----
        if (tid < 64) {
            float bbv = FLT_BIG; int bbi = 0;
#pragma unroll
            for (int gg = 0; gg < 16; gg++) {
                float v = sbv[tid * 17 + gg];
                int   i = sbi[tid * 17 + gg];
                if (v < bbv) { bbv = v; bbi = i; }
            }
            labels[n0 + tid] = (float)bbi;           // float32 output
        }
        __syncthreads();
    }
}

// ---------------- stable counting sort of points by label -------------------------
__global__ void k_hist(const float* __restrict__ labels) {
    __shared__ int h[K_CL];
    const int b = blockIdx.x, tid = threadIdx.x;
    for (int i = tid; i < K_CL; i += 256) h[i] = 0;
    __syncthreads();
    const int s = b * CHUNKB, e = min(N_PTS, s + CHUNKB), m = e - s;
    for (int i = tid; i < m; i += 256) atomicAdd(&h[(int)labels[s + i]], 1);
    __syncthreads();
    for (int i = tid; i < K_CL; i += 256) g_bhist[b][i] = h[i];
}

// parallel scan: per-k totals (unrolled MLP), shfl prefix over k, unrolled run loop
__global__ void k_scan() {
    __shared__ int wsum[8], wpre[8];
    const int k = threadIdx.x;                       // 256 threads, 1 block
    const int lane = k & 31, w = k >> 5;
    int tot = 0;
#pragma unroll 8
    for (int b = 0; b < NSEG; b++) tot += g_bhist[b][k];

    int incl = tot;                                  // warp inclusive scan
#pragma unroll
    for (int off = 1; off < 32; off <<= 1) {
        int v = __shfl_up_sync(0xffffffffu, incl, off);
        if (lane >= off) incl += v;
    }
    if (lane == 31) wsum[w] = incl;
    __syncthreads();
    if (k == 0) {
        int r = 0;
#pragma unroll
        for (int i = 0; i < 8; i++) { wpre[i] = r; r += wsum[i]; }
    }
    __syncthreads();
    int sbase = wpre[w] + incl - tot;                // exclusive prefix

    g_counts[k] = tot;
    g_cbase[k]  = sbase;
    int run = sbase;
#pragma unroll 8
    for (int b = 0; b < NSEG; b++) { g_bbase[b][k] = run; run += g_bhist[b][k]; }
}

// parallel place: thread k owns cluster k, scans slab via smem broadcast
__global__ void k_place(const float* __restrict__ labels) {
    __shared__ int slab[CHUNKB];
    const int b = blockIdx.x, tid = threadIdx.x;     // 256 threads
    const int s = b * CHUNKB, e = min(N_PTS, s + CHUNKB), m = e - s;
    for (int i = tid; i < m; i += 256) slab[i] = (int)labels[s + i];
    __syncthreads();
    int cur = g_bbase[b][tid];                       // tid == cluster k
#pragma unroll 4
    for (int i = 0; i < m; i++) {
        if (slab[i] == tid) g_order[cur++] = s + i;  // stable: ascending i
    }
}

// ---------------- per-cluster serial sums (global point order) + center update ----
__global__ void k_sums(const float* __restrict__ x) {
    __shared__ int sidx[2048];
    const int k = blockIdx.x;                        // 256 blocks
    const int f = threadIdx.x;                       // 64 threads
    const int base = g_cbase[k];
    const int cnt  = g_counts[k];
    float acc = 0.f;
    for (int off = 0; off < cnt; off += 2048) {
        const int m = min(2048, cnt - off);
        __syncthreads();
        for (int i = threadIdx.x; i < m; i += 64) sidx[i] = g_order[base + off + i];
        __syncthreads();
        int i = 0;
        for (; i + 8 <= m; i += 8) {                 // batch loads (MLP), serial adds
            float v0 = x[(size_t)sidx[i + 0] * F_DIM + f];
            float v1 = x[(size_t)sidx[i + 1] * F_DIM + f];
            float v2 = x[(size_t)sidx[i + 2] * F_DIM + f];
            float v3 = x[(size_t)sidx[i + 3] * F_DIM + f];
            float v4 = x[(size_t)sidx[i + 4] * F_DIM + f];
            float v5 = x[(size_t)sidx[i + 5] * F_DIM + f];
            float v6 = x[(size_t)sidx[i + 6] * F_DIM + f];
            float v7 = x[(size_t)sidx[i + 7] * F_DIM + f];
            acc = __fadd_rn(acc, v0); acc = __fadd_rn(acc, v1);
            acc = __fadd_rn(acc, v2); acc = __fadd_rn(acc, v3);
            acc = __fadd_rn(acc, v4); acc = __fadd_rn(acc, v5);
            acc = __fadd_rn(acc, v6); acc = __fadd_rn(acc, v7);
        }
        for (; i < m; i++)
            acc = __fadd_rn(acc, x[(size_t)sidx[i] * F_DIM + f]);
    }
    if (cnt > 0)
        g_centers[k * F_DIM + f] = __fdiv_rn(acc, (float)cnt);  // empty keeps old
}

// ---------------- launch ----------------
extern "C" void kernel_launch(void* const* d_in, const int* in_sizes, int n_in,
                              void* d_out, int out_size) {
    const float* x  = nullptr;
    const float* c0 = nullptr;
    for (int i = 0; i < n_in; i++) {
        if (in_sizes[i] == N_PTS * F_DIM)      x  = (const float*)d_in[i];
        else if (in_sizes[i] == K_CL * F_DIM)  c0 = (const float*)d_in[i];
    }
    if (!x)  x  = (const float*)d_in[0];
    if (!c0) c0 = (const float*)d_in[1];
    float* labels = (float*)d_out;                   // __output__ is float32

    int dev = 0, nsm = 0;
    cudaGetDevice(&dev);
    if (cudaDeviceGetAttribute(&nsm, cudaDevAttrMultiProcessorCount, dev) != cudaSuccess || nsm <= 0)
        nsm = 148;

    const size_t asmem = (size_t)C_TOTAL * sizeof(u64)
                       + 64 * X_STRIDE_F * sizeof(float)
                       + K_CL * sizeof(float)
                       + 64 * 17 * (sizeof(float) + sizeof(int));   // ~90 KB
    cudaFuncSetAttribute(k_assign, cudaFuncAttributeMaxDynamicSharedMemorySize, (int)asmem);

    k_init<<<(N_PTS + 255) / 256, 256>>>(x, c0);
    for (int it = 0; it < MAX_ITERS; it++) {
        k_assign<<<nsm, 512, asmem>>>(x, labels);    // csq fused in prologue
        k_hist<<<NSEG, 256>>>(labels);
        k_scan<<<1, K_CL>>>();
        k_place<<<NSEG, 256>>>(labels);
        k_sums<<<K_CL, F_DIM>>>(x);
    }
}